// round 17
// baseline (speedup 1.0000x reference)
#include <cuda_runtime.h>
#include <cuda_fp16.h>

// ---------------------------------------------------------------------------
// Fused MHA block, all-fp16 mma.sync, ONE persistent pull-queue kernel.
// Queue (1600 items):
//   [0,32)    : prep x row-block        (fp32->fp16)
//   [32,56)   : prep w_qkv col-block
//   [56,64)   : prep w_proj block
//   [64,832)  : QKV tiles, (c8, which, mb) order -> per-column-group release
//   [832,1344): attention tiles, ordered by c8 (gate: qkv col group done)
//   [1344,1600): proj tiles (gate: 16 heads of (b,qb) + wp prep)
// Shapes: B=2, N=2048, EMBED=1024, HEADS=16, HDIM=64.
// ---------------------------------------------------------------------------

#define BATCH  2
#define SEQ    2048
#define EMBED  1024
#define HEADS  16
#define HDIM   64
#define MTOK   (BATCH * SEQ)      // 4096
#define QKVN   (3 * EMBED)        // 3072
#define SCALE  0.125f             // HDIM^-0.5

__device__ __half g_xh[MTOK * EMBED];
__device__ __half g_wqh[QKVN * EMBED];
__device__ __half g_wph[EMBED * EMBED];
__device__ __half g_Qh[BATCH * HEADS * SEQ * HDIM];   // pre-scaled by 0.125
__device__ __half g_Kh[BATCH * HEADS * SEQ * HDIM];
__device__ __half g_Vh[BATCH * HEADS * SEQ * HDIM];
__device__ __half g_Oh[MTOK * EMBED];

// Queue + dependency counters.
__device__ int g_ctr;
__device__ int g_prep_x[32];      // x row-block converted
__device__ int g_prep_wq[24];     // w_qkv col-block converted
__device__ int g_prep_wp;         // w_proj blocks converted (target 8)
__device__ int g_qkv_col[8];      // per head-pair column group (target 96)
__device__ int g_attn_cnt[32];    // per (b*16 + qblock): 16 heads

#define NPREP 64
#define NQKV  768
#define NATT  512
#define NTOT  1600

// ------------------------------- helpers -----------------------------------
__device__ __forceinline__ unsigned pk_f16(float f0, float f1) {
    unsigned d;
    asm("cvt.rn.f16x2.f32 %0, %1, %2;" : "=r"(d) : "f"(f1), "f"(f0));
    return d;
}
__device__ __forceinline__ void mma_f16(float* c, const unsigned* a, const unsigned* b) {
    asm volatile(
        "mma.sync.aligned.m16n8k16.row.col.f32.f16.f16.f32 "
        "{%0,%1,%2,%3}, {%4,%5,%6,%7}, {%8,%9}, {%0,%1,%2,%3};\n"
        : "+f"(c[0]), "+f"(c[1]), "+f"(c[2]), "+f"(c[3])
        : "r"(a[0]), "r"(a[1]), "r"(a[2]), "r"(a[3]),
          "r"(b[0]), "r"(b[1]));
}
__device__ __forceinline__ void ldsm_x4(unsigned& r0, unsigned& r1,
                                        unsigned& r2, unsigned& r3, unsigned addr) {
    asm volatile("ldmatrix.sync.aligned.m8n8.x4.shared.b16 {%0,%1,%2,%3}, [%4];"
                 : "=r"(r0), "=r"(r1), "=r"(r2), "=r"(r3) : "r"(addr));
}
__device__ __forceinline__ void ldsm_x4t(unsigned& r0, unsigned& r1,
                                         unsigned& r2, unsigned& r3, unsigned addr) {
    asm volatile("ldmatrix.sync.aligned.m8n8.x4.trans.shared.b16 {%0,%1,%2,%3}, [%4];"
                 : "=r"(r0), "=r"(r1), "=r"(r2), "=r"(r3) : "r"(addr));
}
__device__ __forceinline__ unsigned smem_u32(const void* p) {
    return (unsigned)__cvta_generic_to_shared(p);
}
#define CP_ASYNC16(dst, src) \
    asm volatile("cp.async.cg.shared.global [%0], [%1], 16;\n" :: "r"(dst), "l"(src))
#define CP_COMMIT() asm volatile("cp.async.commit_group;\n" ::: "memory")
#define CP_WAIT1()  asm volatile("cp.async.wait_group 1;\n" ::: "memory")

__device__ __forceinline__ void wait_cnt(volatile int* c, int target) {
    if (threadIdx.x == 0) { while (*c < target) { } }
    __syncthreads();
}
__device__ __forceinline__ void mark_done(int* c) {
    __threadfence();
    __syncthreads();
    if (threadIdx.x == 0) atomicAdd(c, 1);
}

// ---------------------------------------------------------------------------
// Counter reset (1 block, runs before the persistent kernel).
// ---------------------------------------------------------------------------
__global__ void reset_kernel()
{
    const int tid = threadIdx.x;
    if (tid == 0) { g_ctr = 0; g_prep_wp = 0; }
    if (tid < 32) { g_prep_x[tid] = 0; g_attn_cnt[tid] = 0; }
    if (tid < 24) g_prep_wq[tid] = 0;
    if (tid < 8)  g_qkv_col[tid] = 0;
}

// ---------------------------------------------------------------------------
// Prep tile: convert 32768 float4 (128K floats) to fp16.
// ---------------------------------------------------------------------------
__device__ __forceinline__ void prep_tile(const float* __restrict__ src,
                                          __half* __restrict__ dst)
{
    const float4* s4 = (const float4*)src;
    uint2* d2 = (uint2*)dst;
#pragma unroll 4
    for (int i = threadIdx.x; i < 32768; i += 256) {
        float4 v = s4[i];
        d2[i] = make_uint2(pk_f16(v.x, v.y), pk_f16(v.z, v.w));
    }
}

// ---------------------------------------------------------------------------
// GEMM tile (fp16, BK=64, 3-stage cp.async). mode 0: QKV scatter, 1: proj out.
// ---------------------------------------------------------------------------
#define GSTG  18432
#define GSMEM (3 * 2 * GSTG)       // 110592

__device__ __forceinline__ void gemm_tile(
    const __half* __restrict__ A, const __half* __restrict__ W,
    const float* __restrict__ bias, float* __restrict__ out,
    int N, int m0, int n0, int mode, char* smg, unsigned sbase)
{
    const int K = EMBED;
    const int tid  = threadIdx.x;
    const int wid  = tid >> 5;
    const int lane = tid & 31;
    const int g    = lane >> 2;
    const int t    = lane & 3;
    const int wm0 = (wid & 3) * 32;
    const int wn0 = (wid >> 2) * 64;

    float acc[2][8][4];
#pragma unroll
    for (int mi = 0; mi < 2; ++mi)
#pragma unroll
        for (int nj = 0; nj < 8; ++nj)
#pragma unroll
            for (int r = 0; r < 4; ++r) acc[mi][nj][r] = 0.f;

    const int a_rsub = lane & 15;
    const int a_ko   = (lane >> 4) << 3;
    const int b_rs   = ((lane >> 4) << 3) + (lane & 7);
    const int b_ko   = ((lane >> 3) & 1) << 3;

    auto load_stage = [&](int k0, int slot) {
        const unsigned st = sbase + slot * (2 * GSTG);
#pragma unroll
        for (int i = 0; i < 8; ++i) {
            const int idx = tid + 256 * i;
            const int f   = idx & 1023;
            const int row = f >> 3;
            const int ch  = f & 7;
            const __half* src = (idx < 1024)
                ? &A[(size_t)(m0 + row) * K + k0 + ch * 8]
                : &W[(size_t)(n0 + row) * K + k0 + ch * 8];
            const unsigned dst = st + ((idx < 1024) ? 0 : GSTG) + row * 144 + ch * 16;
            CP_ASYNC16(dst, src);
        }
    };

    const int niter = K / 64;     // 16
    load_stage(0, 0); CP_COMMIT();
    load_stage(64, 1); CP_COMMIT();

    for (int it = 0; it < niter; ++it) {
        CP_WAIT1();
        __syncthreads();
        if (it + 2 < niter) load_stage((it + 2) * 64, (it + 2) % 3);
        CP_COMMIT();

        const unsigned stA = sbase + (it % 3) * (2 * GSTG);
        const unsigned stB = stA + GSTG;
#pragma unroll
        for (int ks = 0; ks < 4; ++ks) {
            unsigned a[2][4];
#pragma unroll
            for (int mi = 0; mi < 2; ++mi) {
                const unsigned off =
                    (unsigned)((wm0 + mi * 16 + a_rsub) * 144 + (ks * 16 + a_ko) * 2);
                ldsm_x4(a[mi][0], a[mi][1], a[mi][2], a[mi][3], stA + off);
            }
#pragma unroll
            for (int njp = 0; njp < 4; ++njp) {
                const unsigned boff =
                    (unsigned)((wn0 + njp * 16 + b_rs) * 144 + (ks * 16 + b_ko) * 2);
                unsigned b[4];
                ldsm_x4(b[0], b[1], b[2], b[3], stB + boff);
#pragma unroll
                for (int mi = 0; mi < 2; ++mi) {
                    mma_f16(acc[mi][2 * njp],     a[mi], b + 0);
                    mma_f16(acc[mi][2 * njp + 1], a[mi], b + 2);
                }
            }
        }
    }
    __syncthreads();               // smem quiescent before next queue item

#pragma unroll
    for (int mi = 0; mi < 2; ++mi) {
#pragma unroll
        for (int nj = 0; nj < 8; ++nj) {
            const int n = n0 + wn0 + nj * 8 + 2 * t;
            const float b0 = bias[n], b1 = bias[n + 1];
#pragma unroll
            for (int half = 0; half < 2; ++half) {
                const int m = m0 + wm0 + mi * 16 + g + half * 8;
                float v0 = acc[mi][nj][2 * half]     + b0;
                float v1 = acc[mi][nj][2 * half + 1] + b1;
                if (mode == 0) {
                    const int which = n >> 10;
                    const int rem   = n & 1023;
                    const int h     = rem >> 6;
                    const int dh    = rem & 63;          // even
                    const int b_    = m >> 11;
                    const int tkn   = m & 2047;
                    if (which == 0) { v0 *= SCALE; v1 *= SCALE; }
                    __half* dst = (which == 0) ? g_Qh : (which == 1) ? g_Kh : g_Vh;
                    *(unsigned*)&dst[(((size_t)(b_ * HEADS + h) * SEQ) + tkn) * HDIM + dh] =
                        pk_f16(v0, v1);
                } else {
                    *(float2*)&out[(size_t)m * N + n] = make_float2(v0, v1);
                }
            }
        }
    }
}

// ---------------------------------------------------------------------------
// Attention tile: fp16 S + PV, 3-stage cp.async KV pipeline.
// ---------------------------------------------------------------------------
#define AQF   0
#define AKV   18432
#define AKVST 18432
#define NKT (SEQ / 64)

__device__ __forceinline__ void attn_tile(int qb, int bh, char* smc, unsigned sbase)
{
    const int q0 = qb * 128;
    const __half* Qp = g_Qh + (size_t)bh * SEQ * HDIM;
    const __half* Kp = g_Kh + (size_t)bh * SEQ * HDIM;
    const __half* Vp = g_Vh + (size_t)bh * SEQ * HDIM;

    const int tid  = threadIdx.x;
    const int wid  = tid >> 5;
    const int lane = tid & 31;
    const int g    = lane >> 2;
    const int t    = lane & 3;
    const int arow = wid * 16;

    auto kv_load = [&](int kt, int slot) {
        const unsigned st = sbase + AKV + slot * AKVST;
#pragma unroll
        for (int i = 0; i < 4; ++i) {
            const int idx = tid + 256 * i;
            const int f   = idx & 511;
            const int row = f >> 3;
            const int ch  = f & 7;
            const __half* src = ((idx < 512) ? Kp : Vp)
                                + (size_t)(kt * 64 + row) * HDIM + ch * 8;
            const unsigned dst = st + ((idx < 512) ? 0 : 9216) + row * 144 + ch * 16;
            CP_ASYNC16(dst, src);
        }
    };

    kv_load(0, 0); CP_COMMIT();
    kv_load(1, 1); CP_COMMIT();

#pragma unroll
    for (int i = 0; i < 4; ++i) {
        const int idx = tid + 256 * i;
        const int r  = idx >> 3;
        const int ch = idx & 7;
        uint4 v = *(const uint4*)&Qp[(size_t)(q0 + r) * HDIM + ch * 8];
        *(uint4*)(smc + AQF + r * 144 + ch * 16) = v;
    }

    float o[8][4];
    float mrow[2] = {-1e30f, -1e30f};
    float lrow[2] = {0.f, 0.f};
#pragma unroll
    for (int nj = 0; nj < 8; ++nj)
#pragma unroll
        for (int r = 0; r < 4; ++r) o[nj][r] = 0.f;

    const unsigned FULL = 0xffffffffu;
    const int q_row = arow + (lane & 15);
    const int q_ko  = (lane >> 4) << 3;
    const int b_rs  = ((lane >> 4) << 3) + (lane & 7);
    const int b_ko  = ((lane >> 3) & 1) << 3;
    const int v_row = (((lane >> 3) & 1) << 3) + (lane & 7);
    const int v_co  = (lane >> 4) << 3;

    for (int kt = 0; kt < NKT; ++kt) {
        CP_WAIT1();
        __syncthreads();
        if (kt + 2 < NKT) kv_load(kt + 2, (kt + 2) % 3);
        CP_COMMIT();

        const unsigned stK = sbase + AKV + (kt % 3) * AKVST;
        const unsigned stV = stK + 9216;

        float s[8][4];
#pragma unroll
        for (int nj = 0; nj < 8; ++nj)
#pragma unroll
            for (int r = 0; r < 4; ++r) s[nj][r] = 0.f;

#pragma unroll
        for (int c16 = 0; c16 < 4; ++c16) {
            const unsigned qoff = (unsigned)(q_row * 144 + (c16 * 16 + q_ko) * 2);
            unsigned a[4];
            ldsm_x4(a[0], a[1], a[2], a[3], sbase + AQF + qoff);
#pragma unroll
            for (int njp = 0; njp < 4; ++njp) {
                const unsigned boff = (unsigned)((njp * 16 + b_rs) * 144
                                                 + (c16 * 16 + b_ko) * 2);
                unsigned b[4];
                ldsm_x4(b[0], b[1], b[2], b[3], stK + boff);
                mma_f16(s[2 * njp],     a, b + 0);
                mma_f16(s[2 * njp + 1], a, b + 2);
            }
        }

#pragma unroll
        for (int h = 0; h < 2; ++h) {
            const int r0 = 2 * h;
            float mx = -1e30f;
#pragma unroll
            for (int nj = 0; nj < 8; ++nj)
                mx = fmaxf(mx, fmaxf(s[nj][r0], s[nj][r0 + 1]));
            mx = fmaxf(mx, __shfl_xor_sync(FULL, mx, 1));
            mx = fmaxf(mx, __shfl_xor_sync(FULL, mx, 2));
            const float mnew = fmaxf(mrow[h], mx);
            const float alpha = __expf(mrow[h] - mnew);
            float rs = 0.f;
#pragma unroll
            for (int nj = 0; nj < 8; ++nj) {
                s[nj][r0]     = __expf(s[nj][r0]     - mnew);
                s[nj][r0 + 1] = __expf(s[nj][r0 + 1] - mnew);
                rs += s[nj][r0] + s[nj][r0 + 1];
            }
            rs += __shfl_xor_sync(FULL, rs, 1);
            rs += __shfl_xor_sync(FULL, rs, 2);
            lrow[h] = alpha * lrow[h] + rs;
            mrow[h] = mnew;
            if (alpha != 1.0f) {
#pragma unroll
                for (int nj = 0; nj < 8; ++nj) {
                    o[nj][r0]     *= alpha;
                    o[nj][r0 + 1] *= alpha;
                }
            }
        }

#pragma unroll
        for (int c16 = 0; c16 < 4; ++c16) {
            unsigned ap[4];
            ap[0] = pk_f16(s[2 * c16][0],     s[2 * c16][1]);
            ap[1] = pk_f16(s[2 * c16][2],     s[2 * c16][3]);
            ap[2] = pk_f16(s[2 * c16 + 1][0], s[2 * c16 + 1][1]);
            ap[3] = pk_f16(s[2 * c16 + 1][2], s[2 * c16 + 1][3]);
            const unsigned vro = (unsigned)((c16 * 16 + v_row) * 144 + v_co * 2);
#pragma unroll
            for (int njp = 0; njp < 4; ++njp) {
                const unsigned voff = vro + (unsigned)(njp * 32);
                unsigned vb[4];
                ldsm_x4t(vb[0], vb[1], vb[2], vb[3], stV + voff);
                mma_f16(o[2 * njp],     ap, vb + 0);
                mma_f16(o[2 * njp + 1], ap, vb + 2);
            }
        }
    }
    __syncthreads();               // smem quiescent before next queue item

    const int h  = bh & (HEADS - 1);
    const int b  = bh >> 4;
    const float inv0 = 1.0f / lrow[0];
    const float inv1 = 1.0f / lrow[1];
    const int r0 = q0 + arow + g;
#pragma unroll
    for (int nj = 0; nj < 8; ++nj) {
        const int col = h * HDIM + nj * 8 + 2 * t;
        *(unsigned*)&g_Oh[(size_t)(b * SEQ + r0) * EMBED + col] =
            pk_f16(o[nj][0] * inv0, o[nj][1] * inv0);
        *(unsigned*)&g_Oh[(size_t)(b * SEQ + r0 + 8) * EMBED + col] =
            pk_f16(o[nj][2] * inv1, o[nj][3] * inv1);
    }
}

// ---------------------------------------------------------------------------
// Persistent fused kernel.
// ---------------------------------------------------------------------------
__global__ __launch_bounds__(256, 2)
void fused_kernel(const float* __restrict__ x,
                  const float* __restrict__ w_qkv,
                  const float* __restrict__ w_proj,
                  const float* __restrict__ b_qkv,
                  const float* __restrict__ b_proj,
                  float* __restrict__ out)
{
    extern __shared__ char smc[];
    const unsigned sbase = smem_u32(smc);
    __shared__ int s_id;

    for (;;) {
        if (threadIdx.x == 0) s_id = atomicAdd(&g_ctr, 1);
        __syncthreads();
        const int id = s_id;
        __syncthreads();
        if (id >= NTOT) return;

        if (id < 32) {                         // prep x row-block
            prep_tile(x + (size_t)id * 131072, g_xh + (size_t)id * 131072);
            mark_done(&g_prep_x[id]);
        } else if (id < 56) {                  // prep w_qkv col-block
            const int j = id - 32;
            prep_tile(w_qkv + (size_t)j * 131072, g_wqh + (size_t)j * 131072);
            mark_done(&g_prep_wq[j]);
        } else if (id < NPREP) {               // prep w_proj block
            const int j = id - 56;
            prep_tile(w_proj + (size_t)j * 131072, g_wph + (size_t)j * 131072);
            mark_done(&g_prep_wp);
        } else if (id < NPREP + NQKV) {
            const int q   = id - NPREP;
            const int c8  = q / 96;            // head-pair column group
            const int rem = q - c8 * 96;
            const int which = rem >> 5;        // 0=Q 1=K 2=V
            const int mb    = rem & 31;
            const int nb    = which * 8 + c8;
            wait_cnt(&g_prep_x[mb], 1);
            wait_cnt(&g_prep_wq[nb], 1);
            gemm_tile(g_xh, g_wqh, b_qkv, nullptr, QKVN,
                      mb * 128, nb * 128, 0, smc, sbase);
            mark_done(&g_qkv_col[c8]);
        } else if (id < NPREP + NQKV + NATT) {
            const int a   = id - NPREP - NQKV;
            const int c8  = a >> 6;            // 0..7
            const int j   = a & 63;
            const int bh4 = j & 3;
            const int qb  = j >> 2;
            const int bh  = (bh4 >> 1) * 16 + 2 * c8 + (bh4 & 1);
            wait_cnt(&g_qkv_col[c8], 96);
            attn_tile(qb, bh, smc, sbase);
            mark_done(&g_attn_cnt[(bh >> 4) * 16 + qb]);
        } else {
            const int p  = id - NPREP - NQKV - NATT;
            const int tt = p >> 3;
            const int nb = p & 7;
            const int qb = tt >> 1;
            const int b  = tt & 1;
            const int mb = b * 16 + qb;
            wait_cnt(&g_prep_wp, 8);
            wait_cnt(&g_attn_cnt[mb], 16);
            gemm_tile(g_Oh, g_wph, b_proj, out, EMBED,
                      mb * 128, nb * 128, 1, smc, sbase);
        }
    }
}

// ---------------------------------------------------------------------------
extern "C" void kernel_launch(void* const* d_in, const int* in_sizes, int n_in,
                              void* d_out, int out_size)
{
    const float* x      = (const float*)d_in[0];
    const float* w_qkv  = (const float*)d_in[1];
    const float* b_qkv  = (const float*)d_in[2];
    const float* w_proj = (const float*)d_in[3];
    const float* b_proj = (const float*)d_in[4];
    float* out = (float*)d_out;

    static int n_sm = 0;
    if (n_sm == 0) {
        cudaDeviceGetAttribute(&n_sm, cudaDevAttrMultiProcessorCount, 0);
        cudaFuncSetAttribute(fused_kernel,
                             cudaFuncAttributeMaxDynamicSharedMemorySize, GSMEM);
    }

    reset_kernel<<<1, 64>>>();
    fused_kernel<<<n_sm * 2, 256, GSMEM>>>(x, w_qkv, w_proj, b_qkv, b_proj, out);
}